// round 16
// baseline (speedup 1.0000x reference)
#include <cuda_runtime.h>
#include <cuda_bf16.h>
#include <cuda_fp16.h>
#include <math.h>
#include <stdint.h>

#define TPB   256
#define PTS   128
#define NBLK  2048

// ---------------- smem layout (bytes), per CTA (~96.5 KB -> 2 CTAs/SM) ----------------
#define SM_A    0u            // A fp16: 128 pts x 384B (192 f16: h[0..127], enc[128..190], bias)
#define SM_W0   49152u        // weight ring buffer 0 (24576B)
#define SM_W1   73728u        // weight ring buffer 1
#define SM_CP   98304u        // 128 x 4B cos_phi
#define SM_MBAR 98816u        // full0, full1, empty0, empty1
#define SM_TOTAL 98848u

// ---------------- global weight scratch (pre-swizzled fp16 smem images) ----------------
#define IMG_L0  0u
#define IMG_HID(l) (16384u + (uint32_t)((l) - 1) * 49152u)   // l = 1..5 (192 rows x 256B)
#define IMG_OUT 262144u                                       // 128 rows x 128B
__device__ __align__(16) unsigned char g_wscratch[278528];

// chunk stream: 12 chunks
//   id 0      : L0 (16384B, 64 rows)          -> W0
//   id 1..10  : hidden l=1..5, 2 x 24576B (96 rows each); odd id -> W1, even -> W0
//   id 11     : out (16384B, 128 rows)        -> W1
__device__ __forceinline__ const unsigned char* chunk_src(int id, uint32_t& sz) {
    if (id == 0)  { sz = 16384u; return g_wscratch + IMG_L0; }
    if (id <= 10) { int t = id - 1; int l = t >> 1; int c = t & 1;
                    sz = 24576u; return g_wscratch + IMG_HID(l + 1) + (uint32_t)c * 24576u; }
    sz = 16384u; return g_wscratch + IMG_OUT;
}

// ---------------- PTX helpers ----------------
__device__ __forceinline__ uint32_t smem_u32(const void* p) {
    uint32_t a;
    asm("{ .reg .u64 t; cvta.to.shared.u64 t, %1; cvt.u32.u64 %0, t; }" : "=r"(a) : "l"(p));
    return a;
}
__device__ __forceinline__ void ldsm_x4(uint32_t& r0, uint32_t& r1, uint32_t& r2, uint32_t& r3, uint32_t a) {
    asm volatile("ldmatrix.sync.aligned.m8n8.x4.shared.b16 {%0,%1,%2,%3}, [%4];"
        : "=r"(r0), "=r"(r1), "=r"(r2), "=r"(r3) : "r"(a));
}
__device__ __forceinline__ void ldsm_x4t(uint32_t& r0, uint32_t& r1, uint32_t& r2, uint32_t& r3, uint32_t a) {
    asm volatile("ldmatrix.sync.aligned.m8n8.x4.trans.shared.b16 {%0,%1,%2,%3}, [%4];"
        : "=r"(r0), "=r"(r1), "=r"(r2), "=r"(r3) : "r"(a));
}
__device__ __forceinline__ void mma_f16(float* d, uint32_t a0, uint32_t a1, uint32_t a2, uint32_t a3,
                                        uint32_t b0, uint32_t b1) {
    asm volatile("mma.sync.aligned.m16n8k16.row.col.f32.f16.f16.f32 "
        "{%0,%1,%2,%3}, {%4,%5,%6,%7}, {%8,%9}, {%0,%1,%2,%3};"
        : "+f"(d[0]), "+f"(d[1]), "+f"(d[2]), "+f"(d[3])
        : "r"(a0), "r"(a1), "r"(a2), "r"(a3), "r"(b0), "r"(b1));
}
#define MBARRIER_INIT(mb, c) asm volatile("mbarrier.init.shared.b64 [%0], %1;" :: "r"((uint32_t)(mb)), "r"((uint32_t)(c)) : "memory")
#define MBARRIER_ARRIVE(mb) asm volatile("mbarrier.arrive.shared.b64 _, [%0];" :: "r"((uint32_t)(mb)) : "memory")
#define MBAR_WAIT(mb, par) do {                                                     \
    uint32_t _mb = (uint32_t)(mb), _p = (uint32_t)(par);                            \
    asm volatile("{\n\t.reg .pred P1;\n\tWL_%=:\n\t"                                \
        "mbarrier.try_wait.parity.acquire.cta.shared::cta.b64 P1, [%0], %1, 0x989680;\n\t" \
        "@P1 bra.uni WD_%=;\n\tbra.uni WL_%=;\n\tWD_%=:\n\t}"                       \
        :: "r"(_mb), "r"(_p) : "memory");                                           \
} while (0)
// one-thread weight fetch: expect_tx + bulk async copy (zero warp issue cost)
__device__ __forceinline__ void w_fetch(uint32_t mb, uint32_t sdst, const unsigned char* gsrc, uint32_t bytes) {
    asm volatile("mbarrier.arrive.expect_tx.shared.b64 _, [%0], %1;"
        :: "r"(mb), "r"(bytes) : "memory");
    asm volatile("cp.async.bulk.shared::cluster.global.mbarrier::complete_tx::bytes [%0], [%1], %2, [%3];"
        :: "r"(sdst), "l"(gsrc), "r"(bytes), "r"(mb) : "memory");
}
__device__ __host__ __forceinline__ uint32_t swz_off(uint32_t row, uint32_t cb, uint32_t rowB) {
    return row * rowB + (cb & ~127u) + ((cb & 127u) ^ ((row & 7u) << 4));
}

// ---------------- weight converter: fp32 -> fp16 swizzled smem images ----------------
__global__ void convert_weights_kernel(const float* __restrict__ W0, const float* __restrict__ b0,
                                       const float* __restrict__ Wh, const float* __restrict__ bh,
                                       const float* __restrict__ Wout)
{
    int idx = blockIdx.x * blockDim.x + threadIdx.x;
    if (idx >= 139264) return;
    float w; uint32_t img, rowB, k, n;
    if (idx < 8192) {                       // L0: K=64 (row 63 = bias), N=128
        k = (uint32_t)(idx >> 7); n = (uint32_t)(idx & 127);
        img = IMG_L0; rowB = 256;
        w = (k < 63) ? W0[k * 128 + n] : b0[n];
    } else if (idx < 131072) {              // hidden: K=192 (row 191 = bias), N=128
        int t = idx - 8192; int l = t / 24576; int r = t % 24576;
        k = (uint32_t)(r >> 7); n = (uint32_t)(r & 127);
        img = IMG_HID(l + 1); rowB = 256;
        w = (k < 191) ? Wh[((uint32_t)l * 191 + k) * 128 + n] : bh[l * 128 + n];
    } else {                                // out: K=128, N=48 padded to 64
        int t = idx - 131072;
        k = (uint32_t)(t >> 6); n = (uint32_t)(t & 63);
        img = IMG_OUT; rowB = 128;
        w = (n < 48) ? Wout[k * 48 + n] : 0.0f;
    }
    uint32_t off = swz_off(k, n * 2, rowB);
    *(__half*)(g_wscratch + img + off) = __float2half_rn(w);
}

// ---------------- small math utils ----------------
__device__ __forceinline__ float3 norm3(float3 v, float eps) {
    float n = sqrtf(v.x * v.x + v.y * v.y + v.z * v.z);
    float inv = 1.0f / fmaxf(n, eps);
    return make_float3(v.x * inv, v.y * inv, v.z * inv);
}
__device__ __forceinline__ float3 cross3(float3 a, float3 b) {
    return make_float3(a.y * b.z - a.z * b.y, a.z * b.x - a.x * b.z, a.x * b.y - a.y * b.x);
}
__device__ __forceinline__ uint32_t packh(float a, float b) {
    __half2 p = __floats2half2_rn(a, b);
    return *(uint32_t*)&p;
}

// ---------------- MMA pass over one weight CHUNK (single fp16 pass) ----------------
template<int KSTEPS, int MT, int NT, int ROWB>
__device__ __forceinline__ void mma_pass(uint32_t sb, uint32_t wreg, int kbaseA,
                                         int m0, int n0, int lane, float (&acc)[MT][NT][4])
{
    const uint32_t l15 = (uint32_t)(lane & 15);
    const uint32_t lh  = (uint32_t)(lane >> 4);
    #pragma unroll
    for (int s = 0; s < KSTEPS; s++) {
        uint32_t b[NT][2];
        #pragma unroll
        for (int t = 0; t < NT / 2; t++) {
            uint32_t krow = (uint32_t)(16 * s) + l15;
            uint32_t cb = (uint32_t)(n0 * 2 + t * 32) + (lh << 4);
            uint32_t off = swz_off(krow, cb, (uint32_t)ROWB);
            ldsm_x4t(b[2 * t][0], b[2 * t][1], b[2 * t + 1][0], b[2 * t + 1][1], sb + wreg + off);
        }
        const uint32_t cbA = (uint32_t)((kbaseA + 16 * s) * 2) + (lh << 4);
        #pragma unroll
        for (int m = 0; m < MT; m++) {
            uint32_t row = (uint32_t)(m0 + 16 * m) + l15;
            uint32_t off = swz_off(row, cbA, 384u);
            uint32_t a0, a1, a2, a3;
            ldsm_x4(a0, a1, a2, a3, sb + SM_A + off);
            #pragma unroll
            for (int n = 0; n < NT; n++) mma_f16(acc[m][n], a0, a1, a2, a3, b[n][0], b[n][1]);
        }
    }
}

// hidden-layer epilogue: leaky-relu, fp16 pack, store into A h-region
__device__ __forceinline__ void epilogue_store(unsigned char* smem, float (&acc)[2][8][4],
                                               int lane, int m0, int n0)
{
    const int r  = lane >> 2;
    const int c2 = (lane & 3) * 2;
    #pragma unroll
    for (int m = 0; m < 2; m++)
        #pragma unroll
        for (int n = 0; n < 8; n++) {
            const uint32_t cb = (uint32_t)((n0 + 8 * n + c2) * 2);
            #pragma unroll
            for (int h = 0; h < 2; h++) {
                uint32_t row = (uint32_t)(m0 + 16 * m + r + 8 * h);
                float v0 = acc[m][n][2 * h + 0];
                float v1 = acc[m][n][2 * h + 1];
                v0 = v0 > 0.0f ? v0 : 0.01f * v0;
                v1 = v1 > 0.0f ? v1 : 0.01f * v1;
                uint32_t off = swz_off(row, cb, 384u);
                *(uint32_t*)(smem + SM_A + off) = packh(v0, v1);
            }
        }
}

// ---------------- main kernel ----------------
extern "C" __global__ void __launch_bounds__(TPB, 2)
fourier_mma_kernel(const float* __restrict__ x, const float* __restrict__ view,
                   const float* __restrict__ normal, const float* __restrict__ light,
                   const float* __restrict__ bout, float* __restrict__ out)
{
    extern __shared__ __align__(16) unsigned char smem[];
    const uint32_t sb = smem_u32(smem);
    const uint32_t mb0  = sb + SM_MBAR;        // full0
    const uint32_t mb1  = sb + SM_MBAR + 8;    // full1
    const uint32_t mbe0 = sb + SM_MBAR + 16;   // empty0 (count 8 = one arrive per warp)
    const uint32_t mbe1 = sb + SM_MBAR + 24;   // empty1
    const int tid  = threadIdx.x;
    const int lane = tid & 31;
    const int warp = tid >> 5;

    // init mbarriers + kick off first two chunk fetches
    if (tid == 0) {
        MBARRIER_INIT(mb0, 1);
        MBARRIER_INIT(mb1, 1);
        MBARRIER_INIT(mbe0, 8);
        MBARRIER_INIT(mbe1, 8);
        uint32_t s0, s1;
        const unsigned char* p0 = chunk_src(0, s0);
        const unsigned char* p1 = chunk_src(1, s1);
        w_fetch(mb0, sb + SM_W0, p0, s0);
        w_fetch(mb1, sb + SM_W1, p1, s1);
    }

    // ---- geometry + cos_phi + Fourier encoding (threads 0..127, thread = point) ----
    if (tid < PTS) {
        const int pt = blockIdx.x * PTS + tid;
        float3 xx = make_float3(x[pt * 3 + 0], x[pt * 3 + 1], x[pt * 3 + 2]);
        float3 vv = make_float3(view[pt * 3 + 0], view[pt * 3 + 1], view[pt * 3 + 2]);
        float3 nn = make_float3(normal[pt * 3 + 0], normal[pt * 3 + 1], normal[pt * 3 + 2]);
        float3 ll = make_float3(light[pt * 3 + 0], light[pt * 3 + 1], light[pt * 3 + 2]);

        float3 n = norm3(nn, 1e-6f);
        float sgn = (n.z >= 0.0f) ? 1.0f : -1.0f;
        float s_z = sgn + n.z;
        float safe = (fabsf(s_z) < 1e-6f) ? copysignf(1e-6f, s_z) : s_z;
        float a = -1.0f / safe;
        float b = n.x * n.y * a;
        float3 s = make_float3(n.x * n.x * a * sgn + 1.0f, b * sgn, -n.x * sgn);
        s = norm3(s, 1e-6f);
        float3 t = norm3(cross3(s, n), 1e-6f);
        s = norm3(cross3(n, t), 1e-6f);

        float3 v = norm3(vv, 1e-6f);
        float3 wo = norm3(make_float3(v.x * s.x + v.y * s.y + v.z * s.z,
                                      v.x * t.x + v.y * t.y + v.z * t.z,
                                      v.x * n.x + v.y * n.y + v.z * n.z), 1e-7f);
        float3 wi = norm3(make_float3(ll.x * s.x + ll.y * s.y + ll.z * s.z,
                                      ll.x * t.x + ll.y * t.y + ll.z * t.z,
                                      ll.x * n.x + ll.y * n.y + ll.z * n.z), 1e-7f);
        float num = -(wi.x * wo.x + wi.y * wo.y);
        float den = sqrtf((wo.x * wo.x + wo.y * wo.y) * (wi.x * wi.x + wi.y * wi.y));
        float cp = fminf(1.0f, fmaxf(-1.0f, num / den));
        *(float*)(smem + SM_CP + tid * 4) = cp;

        float enc[64];
        enc[0] = xx.x; enc[1] = xx.y; enc[2] = xx.z;
        float fr = 1.0f;
        #pragma unroll
        for (int f = 0; f < 10; f++) {
            float sv, cv;
            sincosf(xx.x * fr, &sv, &cv); enc[3 + f * 3 + 0] = sv; enc[33 + f * 3 + 0] = cv;
            sincosf(xx.y * fr, &sv, &cv); enc[3 + f * 3 + 1] = sv; enc[33 + f * 3 + 1] = cv;
            sincosf(xx.z * fr, &sv, &cv); enc[3 + f * 3 + 2] = sv; enc[33 + f * 3 + 2] = cv;
            fr *= 2.0f;
        }
        enc[63] = 1.0f;                      // bias slot

        #pragma unroll
        for (int j = 0; j < 32; j++) {
            uint32_t off = swz_off((uint32_t)tid, 256u + 4u * (uint32_t)j, 384u);
            *(uint32_t*)(smem + SM_A + off) = packh(enc[2 * j], enc[2 * j + 1]);
        }
    }
    __syncthreads();          // A/cp + mbarrier init visible
    uint32_t ph0 = 0, ph1 = 0;   // full-barrier phases (all threads)
    uint32_t pe0 = 0, pe1 = 0;   // empty-barrier phases (thread 0)
    int fid = 2;                 // next chunk to fetch

    // warp tiling: 4 m-groups (32 pts) x 2 n-groups
    const int mg = warp >> 1;
    const int ng = warp & 1;
    const int m0 = mg * 32;
    const int n0h = ng * 64;

    // consume-chunk bookkeeping for buffer parity p (0 -> W0, 1 -> W1)
    #define CHUNK_POST(p)                                                            \
        if (lane == 0) MBARRIER_ARRIVE((p) ? mbe1 : mbe0);                           \
        if (tid == 0 && fid < 12) {                                                  \
            if (p) { MBAR_WAIT(mbe1, pe1); pe1 ^= 1; }                               \
            else   { MBAR_WAIT(mbe0, pe0); pe0 ^= 1; }                               \
            uint32_t s; const unsigned char* q = chunk_src(fid, s);                  \
            w_fetch((p) ? mb1 : mb0, sb + ((p) ? SM_W1 : SM_W0), q, s);              \
        }                                                                            \
        fid++;

    // ================= layer 0: chunk 0 in W0 (64 rows, 4 ksteps) =================
    {
        float acc[2][8][4] = {};
        MBAR_WAIT(mb0, ph0); ph0 ^= 1;
        mma_pass<4, 2, 8, 256>(sb, SM_W0, 128, m0, n0h, lane, acc);
        CHUNK_POST(0)
        // L0 reads enc-cols (bytes 256..383), epilogue writes h-cols (0..255): disjoint
        epilogue_store(smem, acc, lane, m0, n0h);
        __syncthreads();
    }

    // ================= hidden layers 1..5: chunk pair (W1: k0..95, W0: k96..191) =================
    #pragma unroll 1
    for (int l = 1; l <= 5; l++) {
        float acc[2][8][4] = {};
        MBAR_WAIT(mb1, ph1); ph1 ^= 1;
        mma_pass<6, 2, 8, 256>(sb, SM_W1, 0, m0, n0h, lane, acc);
        CHUNK_POST(1)
        MBAR_WAIT(mb0, ph0); ph0 ^= 1;
        mma_pass<6, 2, 8, 256>(sb, SM_W0, 96, m0, n0h, lane, acc);
        CHUNK_POST(0)
        __syncthreads();       // all warps done reading A(l) before overwrite
        epilogue_store(smem, acc, lane, m0, n0h);
        __syncthreads();       // A(l+1) visible
    }

    // ================= output layer: chunk 11 in W1 (128 rows, 8 ksteps) =================
    {
        const int n0o = ng * 32;
        float acc[2][4][4] = {};
        MBAR_WAIT(mb1, ph1); ph1 ^= 1;
        mma_pass<8, 2, 4, 128>(sb, SM_W1, 0, m0, n0o, lane, acc);
        __syncthreads();       // all warps done with A + W buffers

        // stage coeffs into (now dead) A region: [pt][65 f32]
        const int r  = lane >> 2;
        const int c2 = (lane & 3) * 2;
        #pragma unroll
        for (int m = 0; m < 2; m++)
            #pragma unroll
            for (int n = 0; n < 4; n++) {
                int col = n0o + 8 * n + c2;
                #pragma unroll
                for (int h = 0; h < 2; h++) {
                    int row = m0 + 16 * m + r + 8 * h;
                    float* dst = (float*)(smem + SM_A) + row * 65 + col;
                    dst[0] = acc[m][n][2 * h + 0];
                    dst[1] = acc[m][n][2 * h + 1];
                }
            }
        __syncthreads();

        // Chebyshev contraction (threads 0..127, thread = point), cheb recomputed in regs
        if (tid < PTS) {
            float cp = *(float*)(smem + SM_CP + tid * 4);
            float ch[16];
            ch[0] = 1.0f; ch[1] = cp;
            #pragma unroll
            for (int o = 2; o < 16; o++) ch[o] = 2.0f * cp * ch[o - 1] - ch[o - 2];
            const float* cf = (float*)(smem + SM_A) + tid * 65;
            const int pt = blockIdx.x * PTS + tid;
            #pragma unroll
            for (int f = 0; f < 3; f++) {
                float sum = 0.0f;
                #pragma unroll
                for (int o = 0; o < 16; o++)
                    sum += (cf[f * 16 + o] + __ldg(bout + f * 16 + o)) * ch[o];
                out[pt * 3 + f] = sum;
            }
        }
    }
    #undef CHUNK_POST
}

// ---------------- launch ----------------
extern "C" void kernel_launch(void* const* d_in, const int* in_sizes, int n_in,
                              void* d_out, int out_size)
{
    const float* x      = (const float*)d_in[0];
    const float* view   = (const float*)d_in[1];
    const float* normal = (const float*)d_in[2];
    const float* light  = (const float*)d_in[3];
    const float* W0     = (const float*)d_in[4];
    const float* b0     = (const float*)d_in[5];
    const float* Wh     = (const float*)d_in[6];
    const float* bh     = (const float*)d_in[7];
    const float* Wout   = (const float*)d_in[8];
    const float* bout   = (const float*)d_in[9];
    float* out = (float*)d_out;

    convert_weights_kernel<<<544, 256>>>(W0, b0, Wh, bh, Wout);

    cudaFuncSetAttribute(fourier_mma_kernel,
                         cudaFuncAttributeMaxDynamicSharedMemorySize, (int)SM_TOTAL);
    fourier_mma_kernel<<<NBLK, TPB, SM_TOTAL>>>(x, view, normal, light, bout, out);
}

// round 17
// speedup vs baseline: 1.1320x; 1.1320x over previous
#include <cuda_runtime.h>
#include <cuda_bf16.h>
#include <cuda_fp16.h>
#include <math.h>
#include <stdint.h>

#define TPB   128
#define PTS   64
#define NBLK  4096

// ---------------- smem layout (bytes), per CTA (~48.1 KB -> 4 CTAs/SM) ----------------
#define SM_A    0u            // A fp16: 64 pts x 384B (192 f16: h[0..127], enc[128..190], bias)
#define SM_W0   24576u        // weight ring buffer 0 (12288B)
#define SM_W1   36864u        // weight ring buffer 1
#define SM_MBAR 49152u        // full0, full1, empty0, empty1
#define SM_TOTAL 49184u

// ---------------- global weight scratch (pre-swizzled fp16 smem images) ----------------
#define IMG_L0  0u
#define IMG_HID(l) (16384u + (uint32_t)((l) - 1) * 49152u)   // l = 1..5 (192 rows x 256B)
#define IMG_OUT 262144u                                       // 128 rows x 128B
__device__ __align__(16) unsigned char g_wscratch[278528];

// chunk stream: 24 chunks total
//   id 0..1   : L0, 2 x 8192B  (32 rows each)
//   id 2..21  : hidden l=1..5, 4 x 12288B each (48 rows each)
//   id 22..23 : out, 2 x 8192B (64 rows each)
__device__ __forceinline__ const unsigned char* chunk_src(int id, uint32_t& sz) {
    if (id < 2)  { sz = 8192u;  return g_wscratch + IMG_L0 + (uint32_t)id * 8192u; }
    if (id < 22) { int t = id - 2; int l = t >> 2; int c = t & 3;
                   sz = 12288u; return g_wscratch + IMG_HID(l + 1) + (uint32_t)c * 12288u; }
    sz = 8192u; return g_wscratch + IMG_OUT + (uint32_t)(id - 22) * 8192u;
}

// ---------------- PTX helpers ----------------
__device__ __forceinline__ uint32_t smem_u32(const void* p) {
    uint32_t a;
    asm("{ .reg .u64 t; cvta.to.shared.u64 t, %1; cvt.u32.u64 %0, t; }" : "=r"(a) : "l"(p));
    return a;
}
__device__ __forceinline__ void ldsm_x4(uint32_t& r0, uint32_t& r1, uint32_t& r2, uint32_t& r3, uint32_t a) {
    asm volatile("ldmatrix.sync.aligned.m8n8.x4.shared.b16 {%0,%1,%2,%3}, [%4];"
        : "=r"(r0), "=r"(r1), "=r"(r2), "=r"(r3) : "r"(a));
}
__device__ __forceinline__ void ldsm_x4t(uint32_t& r0, uint32_t& r1, uint32_t& r2, uint32_t& r3, uint32_t a) {
    asm volatile("ldmatrix.sync.aligned.m8n8.x4.trans.shared.b16 {%0,%1,%2,%3}, [%4];"
        : "=r"(r0), "=r"(r1), "=r"(r2), "=r"(r3) : "r"(a));
}
__device__ __forceinline__ void mma_f16(float* d, uint32_t a0, uint32_t a1, uint32_t a2, uint32_t a3,
                                        uint32_t b0, uint32_t b1) {
    asm volatile("mma.sync.aligned.m16n8k16.row.col.f32.f16.f16.f32 "
        "{%0,%1,%2,%3}, {%4,%5,%6,%7}, {%8,%9}, {%0,%1,%2,%3};"
        : "+f"(d[0]), "+f"(d[1]), "+f"(d[2]), "+f"(d[3])
        : "r"(a0), "r"(a1), "r"(a2), "r"(a3), "r"(b0), "r"(b1));
}
#define MBARRIER_INIT(mb, c) asm volatile("mbarrier.init.shared.b64 [%0], %1;" :: "r"((uint32_t)(mb)), "r"((uint32_t)(c)) : "memory")
#define MBARRIER_ARRIVE(mb) asm volatile("mbarrier.arrive.shared.b64 _, [%0];" :: "r"((uint32_t)(mb)) : "memory")
#define BAR_PAIR(id) asm volatile("bar.sync %0, 64;" :: "r"(id) : "memory")
#define MBAR_WAIT(mb, par) do {                                                     \
    uint32_t _mb = (uint32_t)(mb), _p = (uint32_t)(par);                            \
    asm volatile("{\n\t.reg .pred P1;\n\tWL_%=:\n\t"                                \
        "mbarrier.try_wait.parity.acquire.cta.shared::cta.b64 P1, [%0], %1, 0x989680;\n\t" \
        "@P1 bra.uni WD_%=;\n\tbra.uni WL_%=;\n\tWD_%=:\n\t}"                       \
        :: "r"(_mb), "r"(_p) : "memory");                                           \
} while (0)
// one-thread weight fetch: expect_tx + bulk async copy (zero warp issue cost)
__device__ __forceinline__ void w_fetch(uint32_t mb, uint32_t sdst, const unsigned char* gsrc, uint32_t bytes) {
    asm volatile("mbarrier.arrive.expect_tx.shared.b64 _, [%0], %1;"
        :: "r"(mb), "r"(bytes) : "memory");
    asm volatile("cp.async.bulk.shared::cluster.global.mbarrier::complete_tx::bytes [%0], [%1], %2, [%3];"
        :: "r"(sdst), "l"(gsrc), "r"(bytes), "r"(mb) : "memory");
}
__device__ __host__ __forceinline__ uint32_t swz_off(uint32_t row, uint32_t cb, uint32_t rowB) {
    return row * rowB + (cb & ~127u) + ((cb & 127u) ^ ((row & 7u) << 4));
}

// fast accurate sincos: Cody-Waite reduce the fp32 argument, then MUFU sin/cos.
// r = a - k*2pi computed with exact-FMA two-term reduction -> |err| ~1e-6 abs.
__device__ __forceinline__ void fsincos(float a, float& s, float& c) {
    float k = rintf(a * 0.15915494309189535f);
    float r = fmaf(k, -6.28318548202514648f, a);     // hi(2pi)
    r = fmaf(k, 1.7484555e-7f, r);                   // -(2pi - hi)
    s = __sinf(r);
    c = __cosf(r);
}

// ---------------- weight converter: fp32 -> fp16 swizzled smem images ----------------
__global__ void convert_weights_kernel(const float* __restrict__ W0, const float* __restrict__ b0,
                                       const float* __restrict__ Wh, const float* __restrict__ bh,
                                       const float* __restrict__ Wout)
{
    int idx = blockIdx.x * blockDim.x + threadIdx.x;
    if (idx >= 139264) return;
    float w; uint32_t img, rowB, k, n;
    if (idx < 8192) {                       // L0: K=64 (row 63 = bias), N=128
        k = (uint32_t)(idx >> 7); n = (uint32_t)(idx & 127);
        img = IMG_L0; rowB = 256;
        w = (k < 63) ? W0[k * 128 + n] : b0[n];
    } else if (idx < 131072) {              // hidden: K=192 (row 191 = bias), N=128
        int t = idx - 8192; int l = t / 24576; int r = t % 24576;
        k = (uint32_t)(r >> 7); n = (uint32_t)(r & 127);
        img = IMG_HID(l + 1); rowB = 256;
        w = (k < 191) ? Wh[((uint32_t)l * 191 + k) * 128 + n] : bh[l * 128 + n];
    } else {                                // out: K=128, N=48 padded to 64
        int t = idx - 131072;
        k = (uint32_t)(t >> 6); n = (uint32_t)(t & 63);
        img = IMG_OUT; rowB = 128;
        w = (n < 48) ? Wout[k * 48 + n] : 0.0f;
    }
    uint32_t off = swz_off(k, n * 2, rowB);
    *(__half*)(g_wscratch + img + off) = __float2half_rn(w);
}

// ---------------- small math utils ----------------
__device__ __forceinline__ float3 norm3(float3 v, float eps) {
    float n = sqrtf(v.x * v.x + v.y * v.y + v.z * v.z);
    float inv = 1.0f / fmaxf(n, eps);
    return make_float3(v.x * inv, v.y * inv, v.z * inv);
}
__device__ __forceinline__ float3 cross3(float3 a, float3 b) {
    return make_float3(a.y * b.z - a.z * b.y, a.z * b.x - a.x * b.z, a.x * b.y - a.y * b.x);
}
__device__ __forceinline__ uint32_t packh(float a, float b) {
    __half2 p = __floats2half2_rn(a, b);
    return *(uint32_t*)&p;
}

// ---------------- MMA pass over one weight CHUNK (single fp16 pass) ----------------
template<int KSTEPS, int MT, int NT, int ROWB>
__device__ __forceinline__ void mma_pass(uint32_t sb, uint32_t wreg, int kbaseA,
                                         int m0, int n0, int lane, float (&acc)[MT][NT][4])
{
    const uint32_t l15 = (uint32_t)(lane & 15);
    const uint32_t lh  = (uint32_t)(lane >> 4);
    #pragma unroll
    for (int s = 0; s < KSTEPS; s++) {
        uint32_t b[NT][2];
        #pragma unroll
        for (int t = 0; t < NT / 2; t++) {
            uint32_t krow = (uint32_t)(16 * s) + l15;
            uint32_t cb = (uint32_t)(n0 * 2 + t * 32) + (lh << 4);
            uint32_t off = swz_off(krow, cb, (uint32_t)ROWB);
            ldsm_x4t(b[2 * t][0], b[2 * t][1], b[2 * t + 1][0], b[2 * t + 1][1], sb + wreg + off);
        }
        const uint32_t cbA = (uint32_t)((kbaseA + 16 * s) * 2) + (lh << 4);
        #pragma unroll
        for (int m = 0; m < MT; m++) {
            uint32_t row = (uint32_t)(m0 + 16 * m) + l15;
            uint32_t off = swz_off(row, cbA, 384u);
            uint32_t a0, a1, a2, a3;
            ldsm_x4(a0, a1, a2, a3, sb + SM_A + off);
            #pragma unroll
            for (int n = 0; n < NT; n++) mma_f16(acc[m][n], a0, a1, a2, a3, b[n][0], b[n][1]);
        }
    }
}

// hidden-layer epilogue: leaky-relu, fp16 pack, store into A h-region
__device__ __forceinline__ void epilogue_store(unsigned char* smem, float (&acc)[2][8][4],
                                               int lane, int m0, int n0)
{
    const int r  = lane >> 2;
    const int c2 = (lane & 3) * 2;
    #pragma unroll
    for (int m = 0; m < 2; m++)
        #pragma unroll
        for (int n = 0; n < 8; n++) {
            const uint32_t cb = (uint32_t)((n0 + 8 * n + c2) * 2);
            #pragma unroll
            for (int h = 0; h < 2; h++) {
                uint32_t row = (uint32_t)(m0 + 16 * m + r + 8 * h);
                float v0 = acc[m][n][2 * h + 0];
                float v1 = acc[m][n][2 * h + 1];
                v0 = v0 > 0.0f ? v0 : 0.01f * v0;
                v1 = v1 > 0.0f ? v1 : 0.01f * v1;
                uint32_t off = swz_off(row, cb, 384u);
                *(uint32_t*)(smem + SM_A + off) = packh(v0, v1);
            }
        }
}

// ---------------- main kernel ----------------
extern "C" __global__ void __launch_bounds__(TPB, 4)
fourier_mma_kernel(const float* __restrict__ x, const float* __restrict__ view,
                   const float* __restrict__ normal, const float* __restrict__ light,
                   const float* __restrict__ bout, float* __restrict__ out)
{
    extern __shared__ __align__(16) unsigned char smem[];
    const uint32_t sb = smem_u32(smem);
    const uint32_t mb0  = sb + SM_MBAR;        // full0
    const uint32_t mb1  = sb + SM_MBAR + 8;    // full1
    const uint32_t mbe0 = sb + SM_MBAR + 16;   // empty0 (count 4 = one arrive per warp)
    const uint32_t mbe1 = sb + SM_MBAR + 24;   // empty1
    const int tid  = threadIdx.x;
    const int lane = tid & 31;
    const int warp = tid >> 5;

    // init mbarriers + kick off first two chunk fetches
    if (tid == 0) {
        MBARRIER_INIT(mb0, 1);
        MBARRIER_INIT(mb1, 1);
        MBARRIER_INIT(mbe0, 4);
        MBARRIER_INIT(mbe1, 4);
        uint32_t s0, s1;
        const unsigned char* p0 = chunk_src(0, s0);
        const unsigned char* p1 = chunk_src(1, s1);
        w_fetch(mb0, sb + SM_W0, p0, s0);
        w_fetch(mb1, sb + SM_W1, p1, s1);
    }

    // ---- geometry + cos_phi + Fourier encoding, split across both thread-halves ----
    // half 0 (t<64): frame + cos_phi + enc cols 0..2, bias, freqs 0..4 of point t
    // half 1 (t>=64): freqs 5..9 of point t-64
    float cp_reg = 0.0f;
    {
        const int half = tid >> 6;
        const int pl   = tid & 63;           // local point = A row
        const int pt   = blockIdx.x * PTS + pl;
        float3 xx = make_float3(x[pt * 3 + 0], x[pt * 3 + 1], x[pt * 3 + 2]);

        if (half == 0) {
            float3 vv = make_float3(view[pt * 3 + 0], view[pt * 3 + 1], view[pt * 3 + 2]);
            float3 nn = make_float3(normal[pt * 3 + 0], normal[pt * 3 + 1], normal[pt * 3 + 2]);
            float3 ll = make_float3(light[pt * 3 + 0], light[pt * 3 + 1], light[pt * 3 + 2]);

            float3 n = norm3(nn, 1e-6f);
            float sgn = (n.z >= 0.0f) ? 1.0f : -1.0f;
            float s_z = sgn + n.z;
            float safe = (fabsf(s_z) < 1e-6f) ? copysignf(1e-6f, s_z) : s_z;
            float a = -1.0f / safe;
            float b = n.x * n.y * a;
            float3 s = make_float3(n.x * n.x * a * sgn + 1.0f, b * sgn, -n.x * sgn);
            s = norm3(s, 1e-6f);
            float3 t = norm3(cross3(s, n), 1e-6f);
            s = norm3(cross3(n, t), 1e-6f);

            float3 v = norm3(vv, 1e-6f);
            float3 wo = norm3(make_float3(v.x * s.x + v.y * s.y + v.z * s.z,
                                          v.x * t.x + v.y * t.y + v.z * t.z,
                                          v.x * n.x + v.y * n.y + v.z * n.z), 1e-7f);
            float3 wi = norm3(make_float3(ll.x * s.x + ll.y * s.y + ll.z * s.z,
                                          ll.x * t.x + ll.y * t.y + ll.z * t.z,
                                          ll.x * n.x + ll.y * n.y + ll.z * n.z), 1e-7f);
            float num = -(wi.x * wo.x + wi.y * wo.y);
            float den = sqrtf((wo.x * wo.x + wo.y * wo.y) * (wi.x * wi.x + wi.y * wi.y));
            cp_reg = fminf(1.0f, fmaxf(-1.0f, num / den));
        }

        // per-column fp16 store into swizzled enc region (A cols 128..191 -> bytes 256..383)
        #define ST_ENC(col, val) do {                                                \
            uint32_t off = swz_off((uint32_t)pl, 256u + 2u * (uint32_t)(col), 384u); \
            *(__half*)(smem + SM_A + off) = __float2half_rn(val);                    \
        } while (0)

        if (half == 0) {
            ST_ENC(0, xx.x); ST_ENC(1, xx.y); ST_ENC(2, xx.z); ST_ENC(63, 1.0f);
        }
        float fr = (half == 0) ? 1.0f : 32.0f;
        const int f0 = (half == 0) ? 0 : 5;
        #pragma unroll
        for (int f = 0; f < 5; f++) {
            float sv, cv;
            fsincos(xx.x * fr, sv, cv); ST_ENC(3 + (f0 + f) * 3 + 0, sv); ST_ENC(33 + (f0 + f) * 3 + 0, cv);
            fsincos(xx.y * fr, sv, cv); ST_ENC(3 + (f0 + f) * 3 + 1, sv); ST_ENC(33 + (f0 + f) * 3 + 1, cv);
            fsincos(xx.z * fr, sv, cv); ST_ENC(3 + (f0 + f) * 3 + 2, sv); ST_ENC(33 + (f0 + f) * 3 + 2, cv);
            fr *= 2.0f;
        }
        #undef ST_ENC
    }
    __syncthreads();          // enc (both halves) + mbarrier init visible
    uint32_t ph0 = 0, ph1 = 0;   // full-barrier phases (all threads)
    uint32_t pe0 = 0, pe1 = 0;   // empty-barrier phases (thread 0)
    int fid = 2;                 // next chunk to fetch

    // warp tiling: 2 m-groups (32 pts) x 2 n-groups; mg pairs are independent on A
    const int mg = warp >> 1;
    const int ng = warp & 1;
    const int m0 = mg * 32;
    const int n0h = ng * 64;
    const int bar_id = 1 + mg;   // named pair barrier (64 threads)

    // per-chunk bookkeeping: arrive empty, thread0 waits empty then refills buffer
    #define CHUNK_POST(c)                                                            \
        if (lane == 0) MBARRIER_ARRIVE((c & 1) ? mbe1 : mbe0);                       \
        if (tid == 0 && fid < 24) {                                                  \
            if (c & 1) { MBAR_WAIT(mbe1, pe1); pe1 ^= 1; }                           \
            else       { MBAR_WAIT(mbe0, pe0); pe0 ^= 1; }                           \
            uint32_t s; const unsigned char* p = chunk_src(fid, s);                  \
            w_fetch((c & 1) ? mb1 : mb0, sb + ((c & 1) ? SM_W1 : SM_W0), p, s);      \
        }                                                                            \
        fid++;

    // ================= layer 0: chunks 0..1 (32 rows each) =================
    {
        float acc[2][8][4] = {};
        #pragma unroll
        for (int c = 0; c < 2; c++) {
            const uint32_t wreg = (c & 1) ? SM_W1 : SM_W0;
            if (c & 1) { MBAR_WAIT(mb1, ph1); ph1 ^= 1; } else { MBAR_WAIT(mb0, ph0); ph0 ^= 1; }
            mma_pass<2, 2, 8, 256>(sb, wreg, 128 + 32 * c, m0, n0h, lane, acc);
            CHUNK_POST(c)
        }
        // L0 reads enc-cols (bytes 256..383), epilogue writes h-cols (0..255): disjoint
        epilogue_store(smem, acc, lane, m0, n0h);
        BAR_PAIR(bar_id);      // partner's A(l=1) rows m0..m0+31 visible
    }

    // ================= hidden layers 1..5: 4 chunks each (48 rows) =================
    #pragma unroll 1
    for (int l = 1; l <= 5; l++) {
        float acc[2][8][4] = {};
        #pragma unroll
        for (int c = 0; c < 4; c++) {
            const uint32_t wreg = (c & 1) ? SM_W1 : SM_W0;
            if (c & 1) { MBAR_WAIT(mb1, ph1); ph1 ^= 1; } else { MBAR_WAIT(mb0, ph0); ph0 ^= 1; }
            mma_pass<3, 2, 8, 256>(sb, wreg, 48 * c, m0, n0h, lane, acc);
            CHUNK_POST(c)
        }
        BAR_PAIR(bar_id);      // pair done reading A(l) rows m0..m0+31
        epilogue_store(smem, acc, lane, m0, n0h);
        BAR_PAIR(bar_id);      // partner's A(l+1) writes visible
    }

    // ================= output layer: chunks 22..23 (64 rows each) =================
    {
        const int n0o = ng * 32;
        float acc[2][4][4] = {};
        #pragma unroll
        for (int c = 0; c < 2; c++) {
            const uint32_t wreg = (c & 1) ? SM_W1 : SM_W0;
            if (c & 1) { MBAR_WAIT(mb1, ph1); ph1 ^= 1; } else { MBAR_WAIT(mb0, ph0); ph0 ^= 1; }
            mma_pass<4, 2, 4, 128>(sb, wreg, 64 * c, m0, n0o, lane, acc);
            CHUNK_POST(c)
        }
        __syncthreads();       // staging region overlaps other pair's A rows -> full sync

        // stage coeffs into (now dead) A region: [pt][65 f32]
        const int r  = lane >> 2;
        const int c2 = (lane & 3) * 2;
        #pragma unroll
        for (int m = 0; m < 2; m++)
            #pragma unroll
            for (int n = 0; n < 4; n++) {
                int col = n0o + 8 * n + c2;
                #pragma unroll
                for (int h = 0; h < 2; h++) {
                    int row = m0 + 16 * m + r + 8 * h;
                    float* dst = (float*)(smem + SM_A) + row * 65 + col;
                    dst[0] = acc[m][n][2 * h + 0];
                    dst[1] = acc[m][n][2 * h + 1];
                }
            }
        __syncthreads();

        // Chebyshev contraction (threads 0..63, thread = point), cheb from cp register
        if (tid < PTS) {
            float ch[16];
            ch[0] = 1.0f; ch[1] = cp_reg;
            #pragma unroll
            for (int o = 2; o < 16; o++) ch[o] = 2.0f * cp_reg * ch[o - 1] - ch[o - 2];
            const float* cf = (float*)(smem + SM_A) + tid * 65;
            const int pt = blockIdx.x * PTS + tid;
            #pragma unroll
            for (int f = 0; f < 3; f++) {
                float sum = 0.0f;
                #pragma unroll
                for (int o = 0; o < 16; o++)
                    sum += (cf[f * 16 + o] + __ldg(bout + f * 16 + o)) * ch[o];
                out[pt * 3 + f] = sum;
            }
        }
    }
    #undef CHUNK_POST
}

// ---------------- launch ----------------
extern "C" void kernel_launch(void* const* d_in, const int* in_sizes, int n_in,
                              void* d_out, int out_size)
{
    const float* x      = (const float*)d_in[0];
    const float* view   = (const float*)d_in[1];
    const float* normal = (const float*)d_in[2];
    const float* light  = (const float*)d_in[3];
    const float* W0     = (const float*)d_in[4];
    const float* b0     = (const float*)d_in[5];
    const float* Wh     = (const float*)d_in[6];
    const float* bh     = (const float*)d_in[7];
    const float* Wout   = (const float*)d_in[8];
    const float* bout   = (const float*)d_in[9];
    float* out = (float*)d_out;

    convert_weights_kernel<<<544, 256>>>(W0, b0, Wh, bh, Wout);

    cudaFuncSetAttribute(fourier_mma_kernel,
                         cudaFuncAttributeMaxDynamicSharedMemorySize, (int)SM_TOTAL);
    fourier_mma_kernel<<<NBLK, TPB, SM_TOTAL>>>(x, view, normal, light, bout, out);
}